// round 13
// baseline (speedup 1.0000x reference)
#include <cuda_runtime.h>
#include <cstdint>

#define H   32
#define TPB 128

typedef unsigned long long u64;

// ---------- packed f32x2 helpers ----------
__device__ __forceinline__ u64 pack2(float lo, float hi) {
    u64 r; asm("mov.b64 %0, {%1, %2};" : "=l"(r) : "f"(lo), "f"(hi)); return r;
}
__device__ __forceinline__ void unpack2(u64 v, float& lo, float& hi) {
    asm("mov.b64 {%0, %1}, %2;" : "=f"(lo), "=f"(hi) : "l"(v));
}
__device__ __forceinline__ u64 ffma2(u64 a, u64 b, u64 c) {
    u64 d; asm("fma.rn.f32x2 %0, %1, %2, %3;" : "=l"(d) : "l"(a), "l"(b), "l"(c)); return d;
}
__device__ __forceinline__ float tanh_mufu(float x) {
    float r; asm("tanh.approx.f32 %0, %1;" : "=f"(r) : "f"(x)); return r;
}
// tanh on a packed pair via MUFU.TANH. Abs err ~4.9e-4 per scalar.
__device__ __forceinline__ u64 tanh2(u64 v) {
    float lo, hi; unpack2(v, lo, hi);
    return pack2(tanh_mufu(lo), tanh_mufu(hi));
}

__device__ __forceinline__ u64 pairAB(float a, float b) {
    return ((u64)__float_as_uint(b) << 32) | (u64)__float_as_uint(a);
}

// Lane packing: lo half = d-network, hi half = o-network.
// Each thread processes TWO rows so every weight LDS feeds 4 FFMA2.
// launch_bounds(128,3): cap regs at 170 -> 3 CTAs/SM -> 12 warps for latency hiding.
__global__ void __launch_bounds__(TPB, 3)
damping_kernel(const float* __restrict__ x,
               const float* __restrict__ wd1, const float* __restrict__ wd2,
               const float* __restrict__ wd3, const float* __restrict__ wo1,
               const float* __restrict__ wo2, const float* __restrict__ wo3,
               const float* __restrict__ bd1, const float* __restrict__ bd2,
               const float* __restrict__ bd3, const float* __restrict__ bo1,
               const float* __restrict__ bo2, const float* __restrict__ bo3,
               float* __restrict__ out, int nPairs)
{
    __shared__ u64 s_w2[H * H];          // {wd2[j][k], wo2[j][k]}
    __shared__ u64 s_w1[2 * H];          // {wd1[i][k], wo1[i][k]}
    __shared__ u64 s_b1[H], s_b2[H];     // {bd*, bo*}
    __shared__ u64 s_w3a[H];             // {wd3[j][0], wo3[j][0]}
    __shared__ u64 s_w3b[H];             // {wd3[j][1], 0}
    __shared__ u64 s_p0, s_q0;           // {bd3[0], bo3[0]}, {bd3[1], 0}

    for (int i = threadIdx.x; i < H * H; i += TPB)
        s_w2[i] = pairAB(wd2[i], wo2[i]);
    for (int i = threadIdx.x; i < 2 * H; i += TPB)
        s_w1[i] = pairAB(wd1[i], wo1[i]);
    for (int i = threadIdx.x; i < H; i += TPB) {
        s_b1[i]  = pairAB(bd1[i], bo1[i]);
        s_b2[i]  = pairAB(bd2[i], bo2[i]);
        s_w3a[i] = pairAB(wd3[2 * i], wo3[i]);
        s_w3b[i] = pairAB(wd3[2 * i + 1], 0.0f);
    }
    if (threadIdx.x == 0) {
        s_p0 = pairAB(bd3[0], bo3[0]);
        s_q0 = pairAB(bd3[1], 0.0f);
    }
    __syncthreads();

    int pair = blockIdx.x * TPB + threadIdx.x;   // rows 2*pair, 2*pair+1
    if (pair >= nPairs) return;

    // x for 2 rows: {x0_r0, x1_r0, x0_r1, x1_r1}
    float4 xv = *reinterpret_cast<const float4*>(x + 4 * (size_t)pair);
    u64 X0a = pairAB(xv.x, xv.x), X1a = pairAB(xv.y, xv.y);
    u64 X0b = pairAB(xv.z, xv.z), X1b = pairAB(xv.w, xv.w);

    // ---- layer 1 (both rows, both nets packed per lane)
    u64 ha[H], hb[H];
    #pragma unroll
    for (int k = 0; k < H; k++) {
        u64 w0 = s_w1[k], w1 = s_w1[H + k], b = s_b1[k];
        ha[k] = tanh2(ffma2(X1a, w1, ffma2(X0a, w0, b)));
        hb[k] = tanh2(ffma2(X1b, w1, ffma2(X0b, w0, b)));
    }

    // ---- layer 2 + 3 fused; 8 accumulator chains (4 outputs x 2 rows)
    u64 Pa = s_p0, Qa = s_q0, Pb = Pa, Qb = Qa;
    #pragma unroll
    for (int kb = 0; kb < H; kb += 4) {
        u64 a0 = s_b2[kb], a1 = s_b2[kb + 1], a2 = s_b2[kb + 2], a3 = s_b2[kb + 3];
        u64 c0 = a0, c1 = a1, c2 = a2, c3 = a3;
        #pragma unroll
        for (int j = 0; j < H; j++) {
            const ulonglong2* wr = reinterpret_cast<const ulonglong2*>(s_w2 + j * H + kb);
            ulonglong2 w01 = wr[0];
            ulonglong2 w23 = wr[1];
            u64 hja = ha[j], hjb = hb[j];
            a0 = ffma2(hja, w01.x, a0);  c0 = ffma2(hjb, w01.x, c0);
            a1 = ffma2(hja, w01.y, a1);  c1 = ffma2(hjb, w01.y, c1);
            a2 = ffma2(hja, w23.x, a2);  c2 = ffma2(hjb, w23.x, c2);
            a3 = ffma2(hja, w23.y, a3);  c3 = ffma2(hjb, w23.y, c3);
        }
        a0 = tanh2(a0); a1 = tanh2(a1); a2 = tanh2(a2); a3 = tanh2(a3);
        c0 = tanh2(c0); c1 = tanh2(c1); c2 = tanh2(c2); c3 = tanh2(c3);
        u64 w3a0 = s_w3a[kb],     w3b0 = s_w3b[kb];
        u64 w3a1 = s_w3a[kb + 1], w3b1 = s_w3b[kb + 1];
        u64 w3a2 = s_w3a[kb + 2], w3b2 = s_w3b[kb + 2];
        u64 w3a3 = s_w3a[kb + 3], w3b3 = s_w3b[kb + 3];
        Pa = ffma2(a0, w3a0, Pa);  Qa = ffma2(a0, w3b0, Qa);
        Pb = ffma2(c0, w3a0, Pb);  Qb = ffma2(c0, w3b0, Qb);
        Pa = ffma2(a1, w3a1, Pa);  Qa = ffma2(a1, w3b1, Qa);
        Pb = ffma2(c1, w3a1, Pb);  Qb = ffma2(c1, w3b1, Qb);
        Pa = ffma2(a2, w3a2, Pa);  Qa = ffma2(a2, w3b2, Qa);
        Pb = ffma2(c2, w3a2, Pb);  Qb = ffma2(c2, w3b2, Qb);
        Pa = ffma2(a3, w3a3, Pa);  Qa = ffma2(a3, w3b3, Qa);
        Pb = ffma2(c3, w3a3, Pb);  Qb = ffma2(c3, w3b3, Qb);
    }

    // ---- epilogue, row a
    float d30, o3v, d31, junk;
    unpack2(Pa, d30, o3v);
    unpack2(Qa, d31, junk);
    float aa = (fmaxf(d30, 0.f) + 0.001f) * xv.x;
    float bb = (fmaxf(d31, 0.f) + 0.001f) * xv.y;
    float cc = o3v;
    float4 ov;
    ov.x = aa * aa * xv.x + aa * cc * xv.y;
    ov.y = aa * cc * xv.x + (cc * cc + bb * bb) * xv.y;

    // ---- epilogue, row b
    unpack2(Pb, d30, o3v);
    unpack2(Qb, d31, junk);
    aa = (fmaxf(d30, 0.f) + 0.001f) * xv.z;
    bb = (fmaxf(d31, 0.f) + 0.001f) * xv.w;
    cc = o3v;
    ov.z = aa * aa * xv.z + aa * cc * xv.w;
    ov.w = aa * cc * xv.z + (cc * cc + bb * bb) * xv.w;

    *reinterpret_cast<float4*>(out + 4 * (size_t)pair) = ov;
}

extern "C" void kernel_launch(void* const* d_in, const int* in_sizes, int n_in,
                              void* d_out, int out_size)
{
    const float* x   = (const float*)d_in[0];
    const float* wd1 = (const float*)d_in[1];
    const float* wd2 = (const float*)d_in[2];
    const float* wd3 = (const float*)d_in[3];
    const float* wo1 = (const float*)d_in[4];
    const float* wo2 = (const float*)d_in[5];
    const float* wo3 = (const float*)d_in[6];
    const float* bd1 = (const float*)d_in[7];
    const float* bd2 = (const float*)d_in[8];
    const float* bd3 = (const float*)d_in[9];
    const float* bo1 = (const float*)d_in[10];
    const float* bo2 = (const float*)d_in[11];
    const float* bo3 = (const float*)d_in[12];
    float* out = (float*)d_out;

    int nRows  = in_sizes[0] / 2;   // x is (B, 2)
    int nPairs = nRows / 2;         // 2 rows per thread
    int blocks = (nPairs + TPB - 1) / TPB;

    damping_kernel<<<blocks, TPB>>>(x, wd1, wd2, wd3, wo1, wo2, wo3,
                                    bd1, bd2, bd3, bo1, bo2, bo3,
                                    out, nPairs);
}

// round 14
// speedup vs baseline: 1.2573x; 1.2573x over previous
#include <cuda_runtime.h>
#include <cstdint>

#define H   32
#define TPB 128

typedef unsigned long long u64;

// ---------- packed f32x2 helpers ----------
__device__ __forceinline__ u64 pack2(float lo, float hi) {
    u64 r; asm("mov.b64 %0, {%1, %2};" : "=l"(r) : "f"(lo), "f"(hi)); return r;
}
__device__ __forceinline__ void unpack2(u64 v, float& lo, float& hi) {
    asm("mov.b64 {%0, %1}, %2;" : "=f"(lo), "=f"(hi) : "l"(v));
}
__device__ __forceinline__ u64 ffma2(u64 a, u64 b, u64 c) {
    u64 d; asm("fma.rn.f32x2 %0, %1, %2, %3;" : "=l"(d) : "l"(a), "l"(b), "l"(c)); return d;
}
__device__ __forceinline__ float tanh_mufu(float x) {
    float r; asm("tanh.approx.f32 %0, %1;" : "=f"(r) : "f"(x)); return r;
}
// tanh on a packed pair via MUFU.TANH. Abs err ~4.9e-4 per scalar.
__device__ __forceinline__ u64 tanh2(u64 v) {
    float lo, hi; unpack2(v, lo, hi);
    return pack2(tanh_mufu(lo), tanh_mufu(hi));
}

__device__ __forceinline__ u64 pairAB(float a, float b) {
    return ((u64)__float_as_uint(b) << 32) | (u64)__float_as_uint(a);
}

// Layer-2 paired weights, duplicated into BOTH smem and constant space.
// The mainloop reads half its weights from each so the smem crossbar and the
// constant-cache port (separate HW paths) each carry ~50% of the traffic.
__constant__ u64 c_w2[H * H];
__device__   u64 g_pair[H * H];   // staging for the constant copy

__global__ void pair_kernel(const float* __restrict__ wd2,
                            const float* __restrict__ wo2)
{
    int i = blockIdx.x * blockDim.x + threadIdx.x;
    if (i < H * H) g_pair[i] = pairAB(wd2[i], wo2[i]);
}

// Lane packing: lo half = d-network, hi half = o-network.
// Each thread processes TWO rows so every weight fetch feeds 4 FFMA2.
__global__ void __launch_bounds__(TPB)
damping_kernel(const float* __restrict__ x,
               const float* __restrict__ wd1, const float* __restrict__ wd2,
               const float* __restrict__ wd3, const float* __restrict__ wo1,
               const float* __restrict__ wo2, const float* __restrict__ wo3,
               const float* __restrict__ bd1, const float* __restrict__ bd2,
               const float* __restrict__ bd3, const float* __restrict__ bo1,
               const float* __restrict__ bo2, const float* __restrict__ bo3,
               float* __restrict__ out, int nPairs)
{
    __shared__ u64 s_w2[H * H];          // {wd2[j][k], wo2[j][k]}
    __shared__ u64 s_w1[2 * H];          // {wd1[i][k], wo1[i][k]}
    __shared__ u64 s_b1[H], s_b2[H];     // {bd*, bo*}
    __shared__ u64 s_w3a[H];             // {wd3[j][0], wo3[j][0]}
    __shared__ u64 s_w3b[H];             // {wd3[j][1], 0}
    __shared__ u64 s_p0, s_q0;           // {bd3[0], bo3[0]}, {bd3[1], 0}

    for (int i = threadIdx.x; i < H * H; i += TPB)
        s_w2[i] = pairAB(wd2[i], wo2[i]);
    for (int i = threadIdx.x; i < 2 * H; i += TPB)
        s_w1[i] = pairAB(wd1[i], wo1[i]);
    for (int i = threadIdx.x; i < H; i += TPB) {
        s_b1[i]  = pairAB(bd1[i], bo1[i]);
        s_b2[i]  = pairAB(bd2[i], bo2[i]);
        s_w3a[i] = pairAB(wd3[2 * i], wo3[i]);
        s_w3b[i] = pairAB(wd3[2 * i + 1], 0.0f);
    }
    if (threadIdx.x == 0) {
        s_p0 = pairAB(bd3[0], bo3[0]);
        s_q0 = pairAB(bd3[1], 0.0f);
    }
    __syncthreads();

    int pair = blockIdx.x * TPB + threadIdx.x;   // rows 2*pair, 2*pair+1
    if (pair >= nPairs) return;

    // x for 2 rows: {x0_r0, x1_r0, x0_r1, x1_r1}
    float4 xv = *reinterpret_cast<const float4*>(x + 4 * (size_t)pair);
    u64 X0a = pairAB(xv.x, xv.x), X1a = pairAB(xv.y, xv.y);
    u64 X0b = pairAB(xv.z, xv.z), X1b = pairAB(xv.w, xv.w);

    // ---- layer 1 (both rows, both nets packed per lane)
    u64 ha[H], hb[H];
    #pragma unroll
    for (int k = 0; k < H; k++) {
        u64 w0 = s_w1[k], w1 = s_w1[H + k], b = s_b1[k];
        ha[k] = tanh2(ffma2(X1a, w1, ffma2(X0a, w0, b)));
        hb[k] = tanh2(ffma2(X1b, w1, ffma2(X0b, w0, b)));
    }

    // ---- layer 2 + 3 fused; 8 accumulator chains (4 outputs x 2 rows)
    // Weight fetch split: k-cols kb,kb+1 from SMEM (LDS.128),
    //                     k-cols kb+2,kb+3 from CONSTANT (LDC) -> parallel ports.
    u64 Pa = s_p0, Qa = s_q0, Pb = Pa, Qb = Qa;
    #pragma unroll
    for (int kb = 0; kb < H; kb += 4) {
        u64 a0 = s_b2[kb], a1 = s_b2[kb + 1], a2 = s_b2[kb + 2], a3 = s_b2[kb + 3];
        u64 c0 = a0, c1 = a1, c2 = a2, c3 = a3;
        #pragma unroll
        for (int j = 0; j < H; j++) {
            ulonglong2 w01 = *reinterpret_cast<const ulonglong2*>(s_w2 + j * H + kb);
            u64 w2c = c_w2[j * H + kb + 2];   // LDC (constant port)
            u64 w3c = c_w2[j * H + kb + 3];   // LDC (constant port)
            u64 hja = ha[j], hjb = hb[j];
            a0 = ffma2(hja, w01.x, a0);  c0 = ffma2(hjb, w01.x, c0);
            a1 = ffma2(hja, w01.y, a1);  c1 = ffma2(hjb, w01.y, c1);
            a2 = ffma2(hja, w2c,   a2);  c2 = ffma2(hjb, w2c,   c2);
            a3 = ffma2(hja, w3c,   a3);  c3 = ffma2(hjb, w3c,   c3);
        }
        a0 = tanh2(a0); a1 = tanh2(a1); a2 = tanh2(a2); a3 = tanh2(a3);
        c0 = tanh2(c0); c1 = tanh2(c1); c2 = tanh2(c2); c3 = tanh2(c3);
        u64 w3a0 = s_w3a[kb],     w3b0 = s_w3b[kb];
        u64 w3a1 = s_w3a[kb + 1], w3b1 = s_w3b[kb + 1];
        u64 w3a2 = s_w3a[kb + 2], w3b2 = s_w3b[kb + 2];
        u64 w3a3 = s_w3a[kb + 3], w3b3 = s_w3b[kb + 3];
        Pa = ffma2(a0, w3a0, Pa);  Qa = ffma2(a0, w3b0, Qa);
        Pb = ffma2(c0, w3a0, Pb);  Qb = ffma2(c0, w3b0, Qb);
        Pa = ffma2(a1, w3a1, Pa);  Qa = ffma2(a1, w3b1, Qa);
        Pb = ffma2(c1, w3a1, Pb);  Qb = ffma2(c1, w3b1, Qb);
        Pa = ffma2(a2, w3a2, Pa);  Qa = ffma2(a2, w3b2, Qa);
        Pb = ffma2(c2, w3a2, Pb);  Qb = ffma2(c2, w3b2, Qb);
        Pa = ffma2(a3, w3a3, Pa);  Qa = ffma2(a3, w3b3, Qa);
        Pb = ffma2(c3, w3a3, Pb);  Qb = ffma2(c3, w3b3, Qb);
    }

    // ---- epilogue, row a
    float d30, o3v, d31, junk;
    unpack2(Pa, d30, o3v);
    unpack2(Qa, d31, junk);
    float aa = (fmaxf(d30, 0.f) + 0.001f) * xv.x;
    float bb = (fmaxf(d31, 0.f) + 0.001f) * xv.y;
    float cc = o3v;
    float4 ov;
    ov.x = aa * aa * xv.x + aa * cc * xv.y;
    ov.y = aa * cc * xv.x + (cc * cc + bb * bb) * xv.y;

    // ---- epilogue, row b
    unpack2(Pb, d30, o3v);
    unpack2(Qb, d31, junk);
    aa = (fmaxf(d30, 0.f) + 0.001f) * xv.z;
    bb = (fmaxf(d31, 0.f) + 0.001f) * xv.w;
    cc = o3v;
    ov.z = aa * aa * xv.z + aa * cc * xv.w;
    ov.w = aa * cc * xv.z + (cc * cc + bb * bb) * xv.w;

    *reinterpret_cast<float4*>(out + 4 * (size_t)pair) = ov;
}

extern "C" void kernel_launch(void* const* d_in, const int* in_sizes, int n_in,
                              void* d_out, int out_size)
{
    const float* x   = (const float*)d_in[0];
    const float* wd1 = (const float*)d_in[1];
    const float* wd2 = (const float*)d_in[2];
    const float* wd3 = (const float*)d_in[3];
    const float* wo1 = (const float*)d_in[4];
    const float* wo2 = (const float*)d_in[5];
    const float* wo3 = (const float*)d_in[6];
    const float* bd1 = (const float*)d_in[7];
    const float* bd2 = (const float*)d_in[8];
    const float* bd3 = (const float*)d_in[9];
    const float* bo1 = (const float*)d_in[10];
    const float* bo2 = (const float*)d_in[11];
    const float* bo3 = (const float*)d_in[12];
    float* out = (float*)d_out;

    // Stage paired layer-2 weights into constant space (all graph-capturable):
    // tiny pairing kernel -> __device__ staging -> contiguous D2D memcpy to symbol.
    pair_kernel<<<(H * H + 127) / 128, 128>>>(wd2, wo2);
    void* symAddr = nullptr;
    void* srcAddr = nullptr;
    cudaGetSymbolAddress(&symAddr, c_w2);
    cudaGetSymbolAddress(&srcAddr, g_pair);
    cudaMemcpyAsync(symAddr, srcAddr, H * H * sizeof(u64),
                    cudaMemcpyDeviceToDevice);

    int nRows  = in_sizes[0] / 2;   // x is (B, 2)
    int nPairs = nRows / 2;         // 2 rows per thread
    int blocks = (nPairs + TPB - 1) / TPB;

    damping_kernel<<<blocks, TPB>>>(x, wd1, wd2, wd3, wo1, wo2, wo3,
                                    bd1, bd2, bd3, bo1, bo2, bo3,
                                    out, nPairs);
}